// round 7
// baseline (speedup 1.0000x reference)
#include <cuda_runtime.h>

#define BS 512
#define TL 128
#define HD 128
#define DZ 32
#define DA 16
#define NB 4

// ---------- device scratch (no allocations allowed) ----------
__device__ float4 gP0ih[DA*HD];
__device__ float4 gP0hh[HD*HD];
__device__ float4 gP1ih[HD*HD];
__device__ float4 gP1hh[HD*HD];
__device__ float4 gB0[HD];
__device__ float4 gB1[HD];
__device__ float  gH1[(size_t)BS*TL*HD];   // hidden seq of layer 1

__device__ __forceinline__ float sigf(float x){ return 1.0f/(1.0f+__expf(-x)); }
__device__ __forceinline__ float clamp4(float x){
    return fminf(fmaxf(x, -1e4f), 1e4f);   // NaN -> -1e4 (bounded)
}

#define FMA4B(acc,w,x) { acc.x=fmaf(w.x,(x),acc.x); acc.y=fmaf(w.y,(x),acc.y); \
                         acc.z=fmaf(w.z,(x),acc.z); acc.w=fmaf(w.w,(x),acc.w); }

// ---------- prep: transpose + gate-pack weights, fold biases ----------
__global__ void k_prep(const float* __restrict__ Wih0, const float* __restrict__ Whh0,
                       const float* __restrict__ Wih1, const float* __restrict__ Whh1,
                       const float* __restrict__ bih0, const float* __restrict__ bhh0,
                       const float* __restrict__ bih1, const float* __restrict__ bhh1)
{
    int id = blockIdx.x*256 + threadIdx.x;
    if (id < DA*HD){
        int k=id/HD, j=id%HD;
        gP0ih[id] = make_float4(Wih0[j*DA+k], Wih0[(j+HD)*DA+k],
                                Wih0[(j+2*HD)*DA+k], Wih0[(j+3*HD)*DA+k]);
    }
    if (id < HD*HD){
        int k=id/HD, j=id%HD;
        gP0hh[id] = make_float4(Whh0[j*HD+k], Whh0[(j+HD)*HD+k],
                                Whh0[(j+2*HD)*HD+k], Whh0[(j+3*HD)*HD+k]);
        gP1ih[id] = make_float4(Wih1[j*HD+k], Wih1[(j+HD)*HD+k],
                                Wih1[(j+2*HD)*HD+k], Wih1[(j+3*HD)*HD+k]);
        gP1hh[id] = make_float4(Whh1[j*HD+k], Whh1[(j+HD)*HD+k],
                                Whh1[(j+2*HD)*HD+k], Whh1[(j+3*HD)*HD+k]);
    }
    if (id < HD){
        gB0[id] = make_float4(bih0[id]+bhh0[id],           bih0[id+HD]+bhh0[id+HD],
                              bih0[id+2*HD]+bhh0[id+2*HD], bih0[id+3*HD]+bhh0[id+3*HD]);
        gB1[id] = make_float4(bih1[id]+bhh1[id],           bih1[id+HD]+bhh1[id+HD],
                              bih1[id+2*HD]+bhh1[id+2*HD], bih1[id+3*HD]+bhh1[id+3*HD]);
    }
}

// ---------- fused 2-layer LSTM scan: 1 block handles NB batch elems ----------
__global__ void __launch_bounds__(HD) k_lstm(const float* __restrict__ a,
                                             const float* __restrict__ a0)
{
    __shared__ float xs[NB][DA];
    __shared__ float h0s[NB][HD];
    __shared__ float h1s[NB][HD];
    int j  = threadIdx.x;
    int b0 = blockIdx.x*NB;
    float c0[NB], c1[NB];
    #pragma unroll
    for (int b=0;b<NB;b++){ c0[b]=0.f; c1[b]=0.f; h0s[b][j]=0.f; h1s[b][j]=0.f; }
    if (j<DA){
        float v=a0[j];
        #pragma unroll
        for (int b=0;b<NB;b++) xs[b][j]=v;
    }
    float4 bv0=gB0[j], bv1=gB1[j];
    __syncthreads();

    for (int t=0;t<TL;t++){
        float4 acc[NB];
        #pragma unroll
        for (int b=0;b<NB;b++) acc[b]=bv0;
        #pragma unroll 4
        for (int k=0;k<DA;k++){
            float4 w = gP0ih[k*HD+j];
            #pragma unroll
            for (int b=0;b<NB;b++){ float x=xs[b][k]; FMA4B(acc[b],w,x); }
        }
        #pragma unroll 4
        for (int k=0;k<HD;k++){
            float4 w = gP0hh[k*HD+j];
            #pragma unroll
            for (int b=0;b<NB;b++){ float x=h0s[b][k]; FMA4B(acc[b],w,x); }
        }
        float hn[NB];
        #pragma unroll
        for (int b=0;b<NB;b++){
            float ii=sigf(acc[b].x), ff=sigf(acc[b].y);
            float gg=tanhf(acc[b].z), oo=sigf(acc[b].w);
            c0[b]=ff*c0[b]+ii*gg;
            hn[b]=oo*tanhf(c0[b]);
        }
        __syncthreads();
        #pragma unroll
        for (int b=0;b<NB;b++) h0s[b][j]=hn[b];
        __syncthreads();

        #pragma unroll
        for (int b=0;b<NB;b++) acc[b]=bv1;
        #pragma unroll 4
        for (int k=0;k<HD;k++){
            float4 w = gP1ih[k*HD+j];
            #pragma unroll
            for (int b=0;b<NB;b++){ float x=h0s[b][k]; FMA4B(acc[b],w,x); }
        }
        #pragma unroll 4
        for (int k=0;k<HD;k++){
            float4 w = gP1hh[k*HD+j];
            #pragma unroll
            for (int b=0;b<NB;b++){ float x=h1s[b][k]; FMA4B(acc[b],w,x); }
        }
        #pragma unroll
        for (int b=0;b<NB;b++){
            float ii=sigf(acc[b].x), ff=sigf(acc[b].y);
            float gg=tanhf(acc[b].z), oo=sigf(acc[b].w);
            c1[b]=ff*c1[b]+ii*gg;
            hn[b]=oo*tanhf(c1[b]);
        }
        __syncthreads();
        #pragma unroll
        for (int b=0;b<NB;b++){
            h1s[b][j]=hn[b];
            gH1[(size_t)((b0+b)*TL+t)*HD+j]=hn[b];
        }
        if (j<DA && t+1<TL){
            #pragma unroll
            for (int b=0;b<NB;b++) xs[b][j]=a[((b0+b)*TL+t)*DA+j];
        }
        __syncthreads();
    }
}

// ---------- Kalman scan: one block per batch element ----------
// Alphas recomputed in-block (guaranteed simplex). Joseph-form covariance
// update (PSD-preserving) + symmetrization: mathematically cannot diverge.
__global__ void __launch_bounds__(128) k_kalman(const float* __restrict__ a,
                                                const float* __restrict__ Am,
                                                const float* __restrict__ Cg,
                                                const float* __restrict__ Wlin,
                                                const float* __restrict__ blin,
                                                float* __restrict__ out)
{
    const int tid  = threadIdx.x;
    const int b    = blockIdx.x;
    const int wd   = tid >> 5;
    const int lane = tid & 31;

    __shared__ float alw[TL][4];       // per-t alphas
    __shared__ float wl[3][HD];        // Wlin rows
    __shared__ float Sg[DZ][DZ+1];     // Sigma_pred
    __shared__ float An[DZ][DZ+1];
    __shared__ float Jm[DZ][DZ+1];     // I - K C
    __shared__ float W1[DZ][DZ+1];
    __shared__ float W2[DZ][DZ+1];
    __shared__ float Cx[DA][DZ+1];
    __shared__ float Mx[DA][DZ+1];     // C*Sigma
    __shared__ float Sa[DA][2*DA+2];   // [S | I]
    __shared__ float Kg[DZ][DA+1];
    __shared__ float mu[DZ], mu2[DZ], rr[DA], atv[DA], frow[DA], rc[DA];

    // ---- prologue: alphas for all t of this batch element ----
    for (int e = tid; e < 3*HD; e += 128) wl[e>>7][e&127] = Wlin[e];
    __syncthreads();
    {
        const float bl0 = blin[0], bl1 = blin[1], bl2 = blin[2];
        for (int t = wd; t < TL; t += 4){
            const float* h = gH1 + ((size_t)b*TL + t)*HD;
            float s0=0.f, s1=0.f, s2=0.f;
            for (int k = lane; k < HD; k += 32){
                float hv = h[k];
                s0 = fmaf(wl[0][k], hv, s0);
                s1 = fmaf(wl[1][k], hv, s1);
                s2 = fmaf(wl[2][k], hv, s2);
            }
            #pragma unroll
            for (int o = 16; o; o >>= 1){
                s0 += __shfl_down_sync(0xffffffffu, s0, o);
                s1 += __shfl_down_sync(0xffffffffu, s1, o);
                s2 += __shfl_down_sync(0xffffffffu, s2, o);
            }
            if (lane == 0){
                s0 += bl0; s1 += bl1; s2 += bl2;
                float m  = fmaxf(s0, fmaxf(s1, s2));
                float e0 = __expf(s0-m), e1 = __expf(s1-m), e2 = __expf(s2-m);
                float inv = 1.f/(e0+e1+e2);
                alw[t][0]=e0*inv; alw[t][1]=e1*inv; alw[t][2]=e2*inv;
            }
        }
    }
    // ---- init state ----
    for (int e = tid; e < DZ*DZ; e += 128){
        int i = e >> 5, j = e & 31;
        Sg[i][j] = (i==j) ? 1.f : 0.f;
    }
    if (tid < DZ) mu[tid] = 0.f;
    __syncthreads();

    const size_t strC = (size_t)TL*DA*DZ, strA = (size_t)TL*DZ*DZ;

    for (int t = 0; t < TL; t++){
        const int tn = (t+1 < TL) ? (t+1) : (TL-1);
        if (tid < DA) atv[tid] = a[(b*TL+t)*DA + tid];
        const float c0 = alw[t][0],  c1 = alw[t][1],  c2 = alw[t][2];
        const float d0 = alw[tn][0], d1 = alw[tn][1], d2 = alw[tn][2];

        // mix C (alpha_t), A_next (alpha_{t+1}, last clamped)
        for (int e = tid; e < DA*DZ; e += 128){
            int i = e >> 5, j = e & 31;
            const float* p = Cg + ((size_t)t*DA + i)*DZ + j;
            Cx[i][j] = c0*p[0] + c1*p[strC] + c2*p[2*strC];
        }
        for (int e = tid; e < DZ*DZ; e += 128){
            int i = e >> 5, j = e & 31;
            const float* p = Am + ((size_t)tn*DZ + i)*DZ + j;
            An[i][j] = d0*p[0] + d1*p[strA] + d2*p[2*strA];
        }
        __syncthreads();

        // M = C*Sigma ; r = a - C*mu
        for (int e = tid; e < DA*DZ; e += 128){
            int i = e >> 5, j = e & 31;
            float s = 0.f;
            for (int k = 0; k < DZ; k++) s = fmaf(Cx[i][k], Sg[k][j], s);
            Mx[i][j] = s;
        }
        if (tid < DA){
            float s = atv[tid];
            for (int k = 0; k < DZ; k++) s = fmaf(-Cx[tid][k], mu[k], s);
            rr[tid] = s;
        }
        __syncthreads();

        // [S | I], S = M*C^T + 0.01 I
        for (int e = tid; e < DA*DA; e += 128){
            int i = e >> 4, j = e & 15;
            float s = (i==j) ? 0.01f : 0.f;
            for (int k = 0; k < DZ; k++) s = fmaf(Mx[i][k], Cx[j][k], s);
            Sa[i][j]    = s;
            Sa[i][DA+j] = (i==j) ? 1.f : 0.f;
        }
        __syncthreads();

        // Gauss-Jordan to diagonal (SPD; guarded pivot)
        for (int p = 0; p < DA; p++){
            if (tid < DA){
                float d = Sa[p][p];
                d = (fabsf(d) > 1e-30f) ? d : 1e-30f;
                frow[tid] = Sa[tid][p] / d;
            }
            __syncthreads();
            for (int e = tid; e < DA*2*DA; e += 128){
                int i = e >> 5, c = e & 31;
                if (i != p) Sa[i][c] = fmaf(-frow[i], Sa[p][c], Sa[i][c]);
            }
            __syncthreads();
        }
        if (tid < DA){
            float d = Sa[tid][tid];
            rc[tid] = 1.0f / ((fabsf(d) > 1e-30f) ? d : 1e-30f);
        }
        __syncthreads();
        for (int e = tid; e < DA*DA; e += 128){
            int i = e >> 4, j = e & 15;
            Sa[i][DA+j] *= rc[i];              // -> S^{-1}
        }
        __syncthreads();

        // Kg = Sigma C^T Sinv = M^T * Sinv  (Sigma symmetric)
        for (int e = tid; e < DZ*DA; e += 128){
            int z = e >> 4, d = e & 15;
            float s = 0.f;
            for (int k = 0; k < DA; k++) s = fmaf(Mx[k][z], Sa[k][DA+d], s);
            Kg[z][d] = s;
        }
        __syncthreads();

        // J = I - Kg*C ; mu_post = mu + Kg*r (OUTPUT)
        for (int e = tid; e < DZ*DZ; e += 128){
            int i = e >> 5, j = e & 31;
            float s = (i==j) ? 1.f : 0.f;
            for (int d = 0; d < DA; d++) s = fmaf(-Kg[i][d], Cx[d][j], s);
            Jm[i][j] = s;
        }
        if (tid < DZ){
            float s = mu[tid];
            for (int d = 0; d < DA; d++) s = fmaf(Kg[tid][d], rr[d], s);
            s = clamp4(s);
            mu2[tid] = s;
            out[((size_t)b*TL + t)*DZ + tid] = s;
        }
        __syncthreads();

        // W1 = J*Sigma
        for (int e = tid; e < DZ*DZ; e += 128){
            int i = e >> 5, j = e & 31;
            float s = 0.f;
            for (int k = 0; k < DZ; k++) s = fmaf(Jm[i][k], Sg[k][j], s);
            W1[i][j] = s;
        }
        __syncthreads();

        // W2 = W1*J^T + 0.01*Kg*Kg^T   (Joseph form)
        for (int e = tid; e < DZ*DZ; e += 128){
            int i = e >> 5, j = e & 31;
            float s = 0.f;
            for (int k = 0; k < DZ; k++) s = fmaf(W1[i][k], Jm[j][k], s);
            float q = 0.f;
            for (int d = 0; d < DA; d++) q = fmaf(Kg[i][d], Kg[j][d], q);
            W2[i][j] = s + 0.01f*q;
        }
        __syncthreads();

        // W1 = sym(W2)  (Sigma_post)
        for (int e = tid; e < DZ*DZ; e += 128){
            int i = e >> 5, j = e & 31;
            W1[i][j] = 0.5f*(W2[i][j] + W2[j][i]);
        }
        __syncthreads();

        // W2 = An * Sigma_post
        for (int e = tid; e < DZ*DZ; e += 128){
            int i = e >> 5, j = e & 31;
            float s = 0.f;
            for (int k = 0; k < DZ; k++) s = fmaf(An[i][k], W1[k][j], s);
            W2[i][j] = s;
        }
        __syncthreads();

        // Sigma_pred' = W2*An^T + 0.01 I ; mu' = An*mu_post
        for (int e = tid; e < DZ*DZ; e += 128){
            int i = e >> 5, j = e & 31;
            float s = (i==j) ? 0.01f : 0.f;
            for (int k = 0; k < DZ; k++) s = fmaf(W2[i][k], An[j][k], s);
            Sg[i][j] = clamp4(s);
        }
        if (tid < DZ){
            float s = 0.f;
            for (int k = 0; k < DZ; k++) s = fmaf(An[tid][k], mu2[k], s);
            mu[tid] = clamp4(s);
        }
        __syncthreads();
    }
}

extern "C" void kernel_launch(void* const* d_in, const int* in_sizes, int n_in,
                              void* d_out, int out_size)
{
    // dict order: a, A, C, a0, Wih0, Whh0, bih0, bhh0, Wih1, Whh1, bih1, bhh1, Wlin, blin
    static const int sig_dict[14] = {1048576,393216,196608,16,8192,65536,512,512,65536,65536,512,512,384,3};
    static const int sig_ascii[14] = {393216,196608,65536,65536,8192,65536,384,1048576,16,512,512,512,512,3};
    static const int map_dict[14]  = {0,1,2,3,4,5,6,7,8,9,10,11,12,13};
    static const int map_ascii[14] = {7,0,1,8,4,2,11,9,5,3,12,10,6,13};

    const int* map = map_dict;
    if (n_in >= 14){
        bool d=true, s=true;
        for (int i=0;i<14;i++){
            if (in_sizes[i]!=sig_dict[i])  d=false;
            if (in_sizes[i]!=sig_ascii[i]) s=false;
        }
        if (!d && s) map = map_ascii;
    }

    const float* a    = (const float*)d_in[map[0]];
    const float* A    = (const float*)d_in[map[1]];
    const float* C    = (const float*)d_in[map[2]];
    const float* a0   = (const float*)d_in[map[3]];
    const float* Wih0 = (const float*)d_in[map[4]];
    const float* Whh0 = (const float*)d_in[map[5]];
    const float* bih0 = (const float*)d_in[map[6]];
    const float* bhh0 = (const float*)d_in[map[7]];
    const float* Wih1 = (const float*)d_in[map[8]];
    const float* Whh1 = (const float*)d_in[map[9]];
    const float* bih1 = (const float*)d_in[map[10]];
    const float* bhh1 = (const float*)d_in[map[11]];
    const float* Wlin = (const float*)d_in[map[12]];
    const float* blin = (const float*)d_in[map[13]];

    k_prep  <<<64, 256>>>(Wih0,Whh0,Wih1,Whh1,bih0,bhh0,bih1,bhh1);
    k_lstm  <<<BS/NB, HD>>>(a, a0);
    k_kalman<<<BS, 128>>>(a, A, C, Wlin, blin, (float*)d_out);
}

// round 9
// speedup vs baseline: 1.1488x; 1.1488x over previous
#include <cuda_runtime.h>

#define BS 512
#define TL 128
#define HD 128
#define DZ 32
#define DA 16
#define NB 4

// ---------- device scratch (no allocations allowed) ----------
__device__ float4 gP0ih[DA*HD];
__device__ float4 gP0hh[HD*HD];
__device__ float4 gP1ih[HD*HD];
__device__ float4 gP1hh[HD*HD];
__device__ float4 gB0[HD];
__device__ float4 gB1[HD];
__device__ float  gH1[(size_t)BS*TL*HD];   // hidden seq of layer 1

__device__ __forceinline__ float sigf(float x){ return 1.0f/(1.0f+__expf(-x)); }
__device__ __forceinline__ float clamp4(float x){
    return fminf(fmaxf(x, -1e4f), 1e4f);   // NaN -> -1e4 (bounded)
}

// NOTE: parameter names must NOT collide with float4 member names (x,y,z,w)
#define FMA4B(acc,vv,ss) { (acc).x=fmaf((vv).x,(ss),(acc).x); (acc).y=fmaf((vv).y,(ss),(acc).y); \
                           (acc).z=fmaf((vv).z,(ss),(acc).z); (acc).w=fmaf((vv).w,(ss),(acc).w); }

// ---------- prep: transpose + gate-pack weights, fold biases ----------
__global__ void k_prep(const float* __restrict__ Wih0, const float* __restrict__ Whh0,
                       const float* __restrict__ Wih1, const float* __restrict__ Whh1,
                       const float* __restrict__ bih0, const float* __restrict__ bhh0,
                       const float* __restrict__ bih1, const float* __restrict__ bhh1)
{
    int id = blockIdx.x*256 + threadIdx.x;
    if (id < DA*HD){
        int k=id/HD, j=id%HD;
        gP0ih[id] = make_float4(Wih0[j*DA+k], Wih0[(j+HD)*DA+k],
                                Wih0[(j+2*HD)*DA+k], Wih0[(j+3*HD)*DA+k]);
    }
    if (id < HD*HD){
        int k=id/HD, j=id%HD;
        gP0hh[id] = make_float4(Whh0[j*HD+k], Whh0[(j+HD)*HD+k],
                                Whh0[(j+2*HD)*HD+k], Whh0[(j+3*HD)*HD+k]);
        gP1ih[id] = make_float4(Wih1[j*HD+k], Wih1[(j+HD)*HD+k],
                                Wih1[(j+2*HD)*HD+k], Wih1[(j+3*HD)*HD+k]);
        gP1hh[id] = make_float4(Whh1[j*HD+k], Whh1[(j+HD)*HD+k],
                                Whh1[(j+2*HD)*HD+k], Whh1[(j+3*HD)*HD+k]);
    }
    if (id < HD){
        gB0[id] = make_float4(bih0[id]+bhh0[id],           bih0[id+HD]+bhh0[id+HD],
                              bih0[id+2*HD]+bhh0[id+2*HD], bih0[id+3*HD]+bhh0[id+3*HD]);
        gB1[id] = make_float4(bih1[id]+bhh1[id],           bih1[id+HD]+bhh1[id+HD],
                              bih1[id+2*HD]+bhh1[id+2*HD], bih1[id+3*HD]+bhh1[id+3*HD]);
    }
}

// ---------- fused 2-layer LSTM scan (unchanged, known good) ----------
__global__ void __launch_bounds__(HD) k_lstm(const float* __restrict__ a,
                                             const float* __restrict__ a0)
{
    __shared__ float xs[NB][DA];
    __shared__ float h0s[NB][HD];
    __shared__ float h1s[NB][HD];
    int j  = threadIdx.x;
    int b0 = blockIdx.x*NB;
    float c0[NB], c1[NB];
    #pragma unroll
    for (int b=0;b<NB;b++){ c0[b]=0.f; c1[b]=0.f; h0s[b][j]=0.f; h1s[b][j]=0.f; }
    if (j<DA){
        float v=a0[j];
        #pragma unroll
        for (int b=0;b<NB;b++) xs[b][j]=v;
    }
    float4 bv0=gB0[j], bv1=gB1[j];
    __syncthreads();

    for (int t=0;t<TL;t++){
        float4 acc[NB];
        #pragma unroll
        for (int b=0;b<NB;b++) acc[b]=bv0;
        #pragma unroll 4
        for (int k=0;k<DA;k++){
            float4 wv = gP0ih[k*HD+j];
            #pragma unroll
            for (int b=0;b<NB;b++){ float xv=xs[b][k]; FMA4B(acc[b],wv,xv); }
        }
        #pragma unroll 4
        for (int k=0;k<HD;k++){
            float4 wv = gP0hh[k*HD+j];
            #pragma unroll
            for (int b=0;b<NB;b++){ float xv=h0s[b][k]; FMA4B(acc[b],wv,xv); }
        }
        float hn[NB];
        #pragma unroll
        for (int b=0;b<NB;b++){
            float ii=sigf(acc[b].x), ff=sigf(acc[b].y);
            float gg=tanhf(acc[b].z), oo=sigf(acc[b].w);
            c0[b]=ff*c0[b]+ii*gg;
            hn[b]=oo*tanhf(c0[b]);
        }
        __syncthreads();
        #pragma unroll
        for (int b=0;b<NB;b++) h0s[b][j]=hn[b];
        __syncthreads();

        #pragma unroll
        for (int b=0;b<NB;b++) acc[b]=bv1;
        #pragma unroll 4
        for (int k=0;k<HD;k++){
            float4 wv = gP1ih[k*HD+j];
            #pragma unroll
            for (int b=0;b<NB;b++){ float xv=h0s[b][k]; FMA4B(acc[b],wv,xv); }
        }
        #pragma unroll 4
        for (int k=0;k<HD;k++){
            float4 wv = gP1hh[k*HD+j];
            #pragma unroll
            for (int b=0;b<NB;b++){ float xv=h1s[b][k]; FMA4B(acc[b],wv,xv); }
        }
        #pragma unroll
        for (int b=0;b<NB;b++){
            float ii=sigf(acc[b].x), ff=sigf(acc[b].y);
            float gg=tanhf(acc[b].z), oo=sigf(acc[b].w);
            c1[b]=ff*c1[b]+ii*gg;
            hn[b]=oo*tanhf(c1[b]);
        }
        __syncthreads();
        #pragma unroll
        for (int b=0;b<NB;b++){
            h1s[b][j]=hn[b];
            gH1[(size_t)((b0+b)*TL+t)*HD+j]=hn[b];
        }
        if (j<DA && t+1<TL){
            #pragma unroll
            for (int b=0;b<NB;b++) xs[b][j]=a[((b0+b)*TL+t)*DA+j];
        }
        __syncthreads();
    }
}

// ---------- Kalman scan: register-tiled, warp-synchronous GJ ----------
#define ST 36   // stride for 32-col tiles (float4-aligned: 144B rows)

__global__ void __launch_bounds__(128) k_kalman(const float* __restrict__ a,
                                                const float* __restrict__ Am,
                                                const float* __restrict__ Cg,
                                                const float* __restrict__ Wlin,
                                                const float* __restrict__ blin,
                                                float* __restrict__ out)
{
    const int tid  = threadIdx.x;
    const int b    = blockIdx.x;
    const int wd   = tid >> 5;
    const int lane = tid & 31;
    const int cgp  = tid & 7;        // col group (4 cols)
    const int rr8  = tid >> 3;       // row pair (0..15)
    const int r0   = rr8*2, r1 = r0+1, c0 = cgp*4;

    __shared__ __align__(16) float Sg [DZ][ST];   // Sigma_pred
    __shared__ __align__(16) float W1 [DZ][ST];
    __shared__ __align__(16) float W2 [DZ][ST];
    __shared__ __align__(16) float An [DZ][ST];
    __shared__ __align__(16) float AnT[DZ][ST];
    __shared__ __align__(16) float Jm [DZ][ST];
    __shared__ __align__(16) float JmT[DZ][ST];
    __shared__ __align__(16) float Cx [DA][ST];
    __shared__ __align__(16) float Mx [DA][ST];
    __shared__ __align__(16) float Kg [DZ][20];
    __shared__ float Sa[DA][18];
    __shared__ __align__(16) float Si[DA][20];
    __shared__ float alw[TL][4];
    __shared__ float wl[3][HD];
    __shared__ float mu[DZ], mu2[DZ], rres[DA], atv[DA];

    // ---- prologue: alphas for all t of this batch element ----
    for (int e = tid; e < 3*HD; e += 128) wl[e>>7][e&127] = Wlin[e];
    __syncthreads();
    {
        const float bl0 = blin[0], bl1 = blin[1], bl2 = blin[2];
        for (int t = wd; t < TL; t += 4){
            const float* h = gH1 + ((size_t)b*TL + t)*HD;
            float s0=0.f, s1=0.f, s2=0.f;
            for (int k = lane; k < HD; k += 32){
                float hv = h[k];
                s0 = fmaf(wl[0][k], hv, s0);
                s1 = fmaf(wl[1][k], hv, s1);
                s2 = fmaf(wl[2][k], hv, s2);
            }
            #pragma unroll
            for (int o = 16; o; o >>= 1){
                s0 += __shfl_down_sync(0xffffffffu, s0, o);
                s1 += __shfl_down_sync(0xffffffffu, s1, o);
                s2 += __shfl_down_sync(0xffffffffu, s2, o);
            }
            if (lane == 0){
                s0 += bl0; s1 += bl1; s2 += bl2;
                float m  = fmaxf(s0, fmaxf(s1, s2));
                float e0 = __expf(s0-m), e1 = __expf(s1-m), e2 = __expf(s2-m);
                float inv = 1.f/(e0+e1+e2);
                alw[t][0]=e0*inv; alw[t][1]=e1*inv; alw[t][2]=e2*inv;
            }
        }
    }
    // ---- init state ----
    for (int e = tid; e < DZ*DZ; e += 128){
        int i = e >> 5, j = e & 31;
        Sg[i][j] = (i==j) ? 1.f : 0.f;
    }
    if (tid < DZ) mu[tid] = 0.f;
    __syncthreads();

    const size_t strC = (size_t)TL*DA*DZ, strA = (size_t)TL*DZ*DZ;

    for (int t = 0; t < TL; t++){
        const int tn = (t+1 < TL) ? (t+1) : (TL-1);
        if (tid < DA) atv[tid] = a[(b*TL+t)*DA + tid];
        const float a0v = alw[t][0],  a1v = alw[t][1],  a2v = alw[t][2];
        const float d0v = alw[tn][0], d1v = alw[tn][1], d2v = alw[tn][2];

        // phase 1: mix Cx (alpha_t), An/AnT (alpha_{t+1})
        for (int e = tid; e < DA*DZ; e += 128){
            int i = e >> 5, j = e & 31;
            const float* p = Cg + ((size_t)t*DA + i)*DZ + j;
            Cx[i][j] = a0v*p[0] + a1v*p[strC] + a2v*p[2*strC];
        }
        for (int e = tid; e < DZ*DZ; e += 128){
            int i = e >> 5, j = e & 31;
            const float* p = Am + ((size_t)tn*DZ + i)*DZ + j;
            float v = d0v*p[0] + d1v*p[strA] + d2v*p[2*strA];
            An[i][j] = v;  AnT[j][i] = v;
        }
        __syncthreads();

        // phase 2: Mx = Cx*Sg (16x32); rres = a - Cx*mu
        {
            int i = tid >> 3;                      // 0..15
            float4 acc = make_float4(0,0,0,0);
            #pragma unroll 8
            for (int k = 0; k < DZ; k++){
                float av = Cx[i][k];
                float4 bv = *reinterpret_cast<const float4*>(&Sg[k][c0]);
                FMA4B(acc, bv, av);
            }
            *reinterpret_cast<float4*>(&Mx[i][c0]) = acc;
        }
        if (tid < DA){
            float s = atv[tid];
            #pragma unroll 8
            for (int k = 0; k < DZ; k++) s = fmaf(-Cx[tid][k], mu[k], s);
            rres[tid] = s;
        }
        __syncthreads();

        // phase 3: S = Mx*Cx^T + 0.01 I  (16x16, f4 dot over k)
        {
            int i = tid >> 3, j0 = (tid & 7)*2;
            float s0 = 0.f, s1 = 0.f;
            #pragma unroll
            for (int kq = 0; kq < 8; kq++){
                float4 m  = *reinterpret_cast<const float4*>(&Mx[i][kq*4]);
                float4 ca = *reinterpret_cast<const float4*>(&Cx[j0][kq*4]);
                float4 cb = *reinterpret_cast<const float4*>(&Cx[j0+1][kq*4]);
                s0 = fmaf(m.x,ca.x, fmaf(m.y,ca.y, fmaf(m.z,ca.z, fmaf(m.w,ca.w, s0))));
                s1 = fmaf(m.x,cb.x, fmaf(m.y,cb.y, fmaf(m.z,cb.z, fmaf(m.w,cb.w, s1))));
            }
            Sa[i][j0]   = s0 + ((i==j0)  ? 0.01f : 0.f);
            Sa[i][j0+1] = s1 + ((i==j0+1)? 0.01f : 0.f);
        }
        __syncthreads();

        // phase 4: warp-0 Gauss-Jordan inverse of S -> Si (columns in regs)
        if (wd == 0){
            float Sc[DA], Ic[DA];
            int c = lane & 15;
            #pragma unroll
            for (int i = 0; i < DA; i++){ Sc[i] = Sa[i][c]; Ic[i] = (i==c)?1.f:0.f; }
            #pragma unroll
            for (int p = 0; p < DA; p++){
                float piv  = __shfl_sync(0xffffffffu, Sc[p], p);
                float invp = 1.f/((fabsf(piv) > 1e-30f) ? piv : 1e-30f);
                float ps = Sc[p], pi = Ic[p];
                #pragma unroll
                for (int i = 0; i < DA; i++){
                    if (i == p) continue;
                    float f = __shfl_sync(0xffffffffu, Sc[i], p) * invp;
                    Sc[i] = fmaf(-f, ps, Sc[i]);
                    Ic[i] = fmaf(-f, pi, Ic[i]);
                }
            }
            #pragma unroll
            for (int i = 0; i < DA; i++){
                float d = __shfl_sync(0xffffffffu, Sc[i], i);
                Ic[i] /= ((fabsf(d) > 1e-30f) ? d : 1e-30f);
            }
            if (lane < DA){
                #pragma unroll
                for (int i = 0; i < DA; i++) Si[i][lane] = Ic[i];
            }
        }
        __syncthreads();

        // phase 5: Kg = Mx^T * Si  (32x16)
        {
            int z = tid >> 2, dg = (tid & 3)*4;
            float4 acc = make_float4(0,0,0,0);
            #pragma unroll
            for (int k = 0; k < DA; k++){
                float av = Mx[k][z];
                float4 bv = *reinterpret_cast<const float4*>(&Si[k][dg]);
                FMA4B(acc, bv, av);
            }
            *reinterpret_cast<float4*>(&Kg[z][dg]) = acc;
        }
        __syncthreads();

        // phase 6: Jm = I - Kg*Cx (+JmT); mu2 = mu + Kg*rres (OUTPUT)
        {
            float4 accA = make_float4((r0==c0)?1.f:0.f, (r0==c0+1)?1.f:0.f,
                                      (r0==c0+2)?1.f:0.f, (r0==c0+3)?1.f:0.f);
            float4 accB = make_float4((r1==c0)?1.f:0.f, (r1==c0+1)?1.f:0.f,
                                      (r1==c0+2)?1.f:0.f, (r1==c0+3)?1.f:0.f);
            #pragma unroll
            for (int d = 0; d < DA; d++){
                float k0 = -Kg[r0][d], k1 = -Kg[r1][d];
                float4 cv = *reinterpret_cast<const float4*>(&Cx[d][c0]);
                FMA4B(accA, cv, k0);
                FMA4B(accB, cv, k1);
            }
            *reinterpret_cast<float4*>(&Jm[r0][c0]) = accA;
            *reinterpret_cast<float4*>(&Jm[r1][c0]) = accB;
            JmT[c0  ][r0]=accA.x; JmT[c0+1][r0]=accA.y; JmT[c0+2][r0]=accA.z; JmT[c0+3][r0]=accA.w;
            JmT[c0  ][r1]=accB.x; JmT[c0+1][r1]=accB.y; JmT[c0+2][r1]=accB.z; JmT[c0+3][r1]=accB.w;
        }
        if (tid < DZ){
            float s = mu[tid];
            #pragma unroll
            for (int d = 0; d < DA; d++) s = fmaf(Kg[tid][d], rres[d], s);
            s = clamp4(s);
            mu2[tid] = s;
            out[((size_t)b*TL + t)*DZ + tid] = s;
        }
        __syncthreads();

        // phase 7: W1 = Jm*Sg
        {
            float4 accA = make_float4(0,0,0,0), accB = make_float4(0,0,0,0);
            #pragma unroll 8
            for (int k = 0; k < DZ; k++){
                float jA = Jm[r0][k], jB = Jm[r1][k];
                float4 sv = *reinterpret_cast<const float4*>(&Sg[k][c0]);
                FMA4B(accA, sv, jA);
                FMA4B(accB, sv, jB);
            }
            *reinterpret_cast<float4*>(&W1[r0][c0]) = accA;
            *reinterpret_cast<float4*>(&W1[r1][c0]) = accB;
        }
        __syncthreads();

        // phase 8: W2 = W1*Jm^T + 0.01*Kg*Kg^T   (Joseph form)
        {
            float4 accA = make_float4(0,0,0,0), accB = make_float4(0,0,0,0);
            #pragma unroll 8
            for (int k = 0; k < DZ; k++){
                float wA = W1[r0][k], wB = W1[r1][k];
                float4 jv = *reinterpret_cast<const float4*>(&JmT[k][c0]);
                FMA4B(accA, jv, wA);
                FMA4B(accB, jv, wB);
            }
            float4 qA = make_float4(0,0,0,0), qB = make_float4(0,0,0,0);
            #pragma unroll
            for (int dq = 0; dq < 4; dq++){
                float4 ka = *reinterpret_cast<const float4*>(&Kg[r0][dq*4]);
                float4 kb = *reinterpret_cast<const float4*>(&Kg[r1][dq*4]);
                float4 kc0 = *reinterpret_cast<const float4*>(&Kg[c0  ][dq*4]);
                float4 kc1 = *reinterpret_cast<const float4*>(&Kg[c0+1][dq*4]);
                float4 kc2 = *reinterpret_cast<const float4*>(&Kg[c0+2][dq*4]);
                float4 kc3 = *reinterpret_cast<const float4*>(&Kg[c0+3][dq*4]);
                qA.x = fmaf(ka.x,kc0.x,fmaf(ka.y,kc0.y,fmaf(ka.z,kc0.z,fmaf(ka.w,kc0.w,qA.x))));
                qA.y = fmaf(ka.x,kc1.x,fmaf(ka.y,kc1.y,fmaf(ka.z,kc1.z,fmaf(ka.w,kc1.w,qA.y))));
                qA.z = fmaf(ka.x,kc2.x,fmaf(ka.y,kc2.y,fmaf(ka.z,kc2.z,fmaf(ka.w,kc2.w,qA.z))));
                qA.w = fmaf(ka.x,kc3.x,fmaf(ka.y,kc3.y,fmaf(ka.z,kc3.z,fmaf(ka.w,kc3.w,qA.w))));
                qB.x = fmaf(kb.x,kc0.x,fmaf(kb.y,kc0.y,fmaf(kb.z,kc0.z,fmaf(kb.w,kc0.w,qB.x))));
                qB.y = fmaf(kb.x,kc1.x,fmaf(kb.y,kc1.y,fmaf(kb.z,kc1.z,fmaf(kb.w,kc1.w,qB.y))));
                qB.z = fmaf(kb.x,kc2.x,fmaf(kb.y,kc2.y,fmaf(kb.z,kc2.z,fmaf(kb.w,kc2.w,qB.z))));
                qB.w = fmaf(kb.x,kc3.x,fmaf(kb.y,kc3.y,fmaf(kb.z,kc3.z,fmaf(kb.w,kc3.w,qB.w))));
            }
            accA.x += 0.01f*qA.x; accA.y += 0.01f*qA.y; accA.z += 0.01f*qA.z; accA.w += 0.01f*qA.w;
            accB.x += 0.01f*qB.x; accB.y += 0.01f*qB.y; accB.z += 0.01f*qB.z; accB.w += 0.01f*qB.w;
            *reinterpret_cast<float4*>(&W2[r0][c0]) = accA;
            *reinterpret_cast<float4*>(&W2[r1][c0]) = accB;
        }
        __syncthreads();

        // phase 9: W1 = sym(W2)  (Sigma_post)
        {
            #pragma unroll
            for (int q = 0; q < 4; q++){
                W1[r0][c0+q] = 0.5f*(W2[r0][c0+q] + W2[c0+q][r0]);
                W1[r1][c0+q] = 0.5f*(W2[r1][c0+q] + W2[c0+q][r1]);
            }
        }
        __syncthreads();

        // phase 10: W2 = An * Sigma_post
        {
            float4 accA = make_float4(0,0,0,0), accB = make_float4(0,0,0,0);
            #pragma unroll 8
            for (int k = 0; k < DZ; k++){
                float aA = An[r0][k], aB = An[r1][k];
                float4 wv = *reinterpret_cast<const float4*>(&W1[k][c0]);
                FMA4B(accA, wv, aA);
                FMA4B(accB, wv, aB);
            }
            *reinterpret_cast<float4*>(&W2[r0][c0]) = accA;
            *reinterpret_cast<float4*>(&W2[r1][c0]) = accB;
        }
        __syncthreads();

        // phase 11: Sg = W2*An^T + 0.01 I ; mu' = An*mu2
        {
            float4 accA = make_float4((r0==c0)?0.01f:0.f, (r0==c0+1)?0.01f:0.f,
                                      (r0==c0+2)?0.01f:0.f, (r0==c0+3)?0.01f:0.f);
            float4 accB = make_float4((r1==c0)?0.01f:0.f, (r1==c0+1)?0.01f:0.f,
                                      (r1==c0+2)?0.01f:0.f, (r1==c0+3)?0.01f:0.f);
            #pragma unroll 8
            for (int k = 0; k < DZ; k++){
                float wA = W2[r0][k], wB = W2[r1][k];
                float4 av = *reinterpret_cast<const float4*>(&AnT[k][c0]);
                FMA4B(accA, av, wA);
                FMA4B(accB, av, wB);
            }
            accA.x=clamp4(accA.x); accA.y=clamp4(accA.y); accA.z=clamp4(accA.z); accA.w=clamp4(accA.w);
            accB.x=clamp4(accB.x); accB.y=clamp4(accB.y); accB.z=clamp4(accB.z); accB.w=clamp4(accB.w);
            *reinterpret_cast<float4*>(&Sg[r0][c0]) = accA;
            *reinterpret_cast<float4*>(&Sg[r1][c0]) = accB;
        }
        if (tid < DZ){
            float s = 0.f;
            #pragma unroll 8
            for (int k = 0; k < DZ; k++) s = fmaf(An[tid][k], mu2[k], s);
            mu[tid] = clamp4(s);
        }
        __syncthreads();
    }
}

extern "C" void kernel_launch(void* const* d_in, const int* in_sizes, int n_in,
                              void* d_out, int out_size)
{
    // dict order: a, A, C, a0, Wih0, Whh0, bih0, bhh0, Wih1, Whh1, bih1, bhh1, Wlin, blin
    static const int sig_dict[14] = {1048576,393216,196608,16,8192,65536,512,512,65536,65536,512,512,384,3};
    static const int sig_ascii[14] = {393216,196608,65536,65536,8192,65536,384,1048576,16,512,512,512,512,3};
    static const int map_dict[14]  = {0,1,2,3,4,5,6,7,8,9,10,11,12,13};
    static const int map_ascii[14] = {7,0,1,8,4,2,11,9,5,3,12,10,6,13};

    const int* map = map_dict;
    if (n_in >= 14){
        bool d=true, s=true;
        for (int i=0;i<14;i++){
            if (in_sizes[i]!=sig_dict[i])  d=false;
            if (in_sizes[i]!=sig_ascii[i]) s=false;
        }
        if (!d && s) map = map_ascii;
    }

    const float* a    = (const float*)d_in[map[0]];
    const float* A    = (const float*)d_in[map[1]];
    const float* C    = (const float*)d_in[map[2]];
    const float* a0   = (const float*)d_in[map[3]];
    const float* Wih0 = (const float*)d_in[map[4]];
    const float* Whh0 = (const float*)d_in[map[5]];
    const float* bih0 = (const float*)d_in[map[6]];
    const float* bhh0 = (const float*)d_in[map[7]];
    const float* Wih1 = (const float*)d_in[map[8]];
    const float* Whh1 = (const float*)d_in[map[9]];
    const float* bih1 = (const float*)d_in[map[10]];
    const float* bhh1 = (const float*)d_in[map[11]];
    const float* Wlin = (const float*)d_in[map[12]];
    const float* blin = (const float*)d_in[map[13]];

    k_prep  <<<64, 256>>>(Wih0,Whh0,Wih1,Whh1,bih0,bhh0,bih1,bhh1);
    k_lstm  <<<BS/NB, HD>>>(a, a0);
    k_kalman<<<BS, 128>>>(a, A, C, Wlin, blin, (float*)d_out);
}

// round 10
// speedup vs baseline: 1.1506x; 1.0015x over previous
#include <cuda_runtime.h>

#define BS 512
#define TL 128
#define HD 128
#define DZ 32
#define DA 16
#define NB 4

typedef unsigned long long u64;

// ---------- device scratch (no allocations allowed) ----------
__device__ float4 gP0ih[DA*HD];
__device__ float4 gP0hh[HD*HD];
__device__ float4 gP1ih[HD*HD];
__device__ float4 gP1hh[HD*HD];
__device__ float4 gB0[HD];
__device__ float4 gB1[HD];
__device__ float  gH1[(size_t)BS*TL*HD];   // hidden seq of layer 1

__device__ __forceinline__ float sigf(float x){ return 1.0f/(1.0f+__expf(-x)); }
__device__ __forceinline__ float clamp4(float x){
    return fminf(fmaxf(x, -1e4f), 1e4f);   // NaN -> -1e4 (bounded)
}

// ---- packed f32x2 helpers (Blackwell; PTX-only, ptxas won't auto-fuse) ----
__device__ __forceinline__ void ffma2(u64& acc, u64 a, u64 b){
    asm("fma.rn.f32x2 %0, %1, %2, %0;" : "+l"(acc) : "l"(a), "l"(b));
}
__device__ __forceinline__ u64 pk2(float s){
    u64 r; asm("mov.b64 %0, {%1, %1};" : "=l"(r) : "f"(s)); return r;
}
__device__ __forceinline__ float2 up2(u64 v){
    float lo, hi; asm("mov.b64 {%0, %1}, %2;" : "=f"(lo), "=f"(hi) : "l"(v));
    return make_float2(lo, hi);
}
union F4U { float4 f; ulonglong2 u; };

// NOTE: parameter names must NOT collide with float4 member names
#define FMA4B(acc,vv,ss) { (acc).x=fmaf((vv).x,(ss),(acc).x); (acc).y=fmaf((vv).y,(ss),(acc).y); \
                           (acc).z=fmaf((vv).z,(ss),(acc).z); (acc).w=fmaf((vv).w,(ss),(acc).w); }

// ---------- prep: transpose + gate-pack weights, fold biases ----------
__global__ void k_prep(const float* __restrict__ Wih0, const float* __restrict__ Whh0,
                       const float* __restrict__ Wih1, const float* __restrict__ Whh1,
                       const float* __restrict__ bih0, const float* __restrict__ bhh0,
                       const float* __restrict__ bih1, const float* __restrict__ bhh1)
{
    int id = blockIdx.x*256 + threadIdx.x;
    if (id < DA*HD){
        int k=id/HD, j=id%HD;
        gP0ih[id] = make_float4(Wih0[j*DA+k], Wih0[(j+HD)*DA+k],
                                Wih0[(j+2*HD)*DA+k], Wih0[(j+3*HD)*DA+k]);
    }
    if (id < HD*HD){
        int k=id/HD, j=id%HD;
        gP0hh[id] = make_float4(Whh0[j*HD+k], Whh0[(j+HD)*HD+k],
                                Whh0[(j+2*HD)*HD+k], Whh0[(j+3*HD)*HD+k]);
        gP1ih[id] = make_float4(Wih1[j*HD+k], Wih1[(j+HD)*HD+k],
                                Wih1[(j+2*HD)*HD+k], Wih1[(j+3*HD)*HD+k]);
        gP1hh[id] = make_float4(Whh1[j*HD+k], Whh1[(j+HD)*HD+k],
                                Whh1[(j+2*HD)*HD+k], Whh1[(j+3*HD)*HD+k]);
    }
    if (id < HD){
        gB0[id] = make_float4(bih0[id]+bhh0[id],           bih0[id+HD]+bhh0[id+HD],
                              bih0[id+2*HD]+bhh0[id+2*HD], bih0[id+3*HD]+bhh0[id+3*HD]);
        gB1[id] = make_float4(bih1[id]+bhh1[id],           bih1[id+HD]+bhh1[id+HD],
                              bih1[id+2*HD]+bhh1[id+2*HD], bih1[id+3*HD]+bhh1[id+3*HD]);
    }
}

// ---------- fused 2-layer LSTM scan: packed f32x2 gates ----------
__global__ void __launch_bounds__(HD) k_lstm(const float* __restrict__ a,
                                             const float* __restrict__ a0)
{
    __shared__ float xs[NB][DA];
    __shared__ float h0s[NB][HD];
    __shared__ float h1s[NB][HD];
    int j  = threadIdx.x;
    int b0 = blockIdx.x*NB;
    float c0[NB], c1[NB];
    #pragma unroll
    for (int b=0;b<NB;b++){ c0[b]=0.f; c1[b]=0.f; h0s[b][j]=0.f; h1s[b][j]=0.f; }
    if (j<DA){
        float v=a0[j];
        #pragma unroll
        for (int b=0;b<NB;b++) xs[b][j]=v;
    }
    F4U bv0, bv1; bv0.f = gB0[j]; bv1.f = gB1[j];
    __syncthreads();

    for (int t=0;t<TL;t++){
        // ---- layer 0 gates (packed) ----
        u64 aLo[NB], aHi[NB];
        #pragma unroll
        for (int b=0;b<NB;b++){ aLo[b]=bv0.u.x; aHi[b]=bv0.u.y; }
        #pragma unroll 4
        for (int k=0;k<DA;k++){
            F4U wv; wv.f = gP0ih[k*HD+j];
            #pragma unroll
            for (int b=0;b<NB;b++){
                u64 x2 = pk2(xs[b][k]);
                ffma2(aLo[b], wv.u.x, x2);
                ffma2(aHi[b], wv.u.y, x2);
            }
        }
        #pragma unroll 4
        for (int k=0;k<HD;k++){
            F4U wv; wv.f = gP0hh[k*HD+j];
            #pragma unroll
            for (int b=0;b<NB;b++){
                u64 x2 = pk2(h0s[b][k]);
                ffma2(aLo[b], wv.u.x, x2);
                ffma2(aHi[b], wv.u.y, x2);
            }
        }
        float hn[NB];
        #pragma unroll
        for (int b=0;b<NB;b++){
            float2 ifg = up2(aLo[b]);     // (i, f)
            float2 go  = up2(aHi[b]);     // (g, o)
            float ii=sigf(ifg.x), ff=sigf(ifg.y);
            float gg=tanhf(go.x),  oo=sigf(go.y);
            c0[b]=ff*c0[b]+ii*gg;
            hn[b]=oo*tanhf(c0[b]);
        }
        __syncthreads();
        #pragma unroll
        for (int b=0;b<NB;b++) h0s[b][j]=hn[b];
        __syncthreads();

        // ---- layer 1 gates (packed) ----
        #pragma unroll
        for (int b=0;b<NB;b++){ aLo[b]=bv1.u.x; aHi[b]=bv1.u.y; }
        #pragma unroll 4
        for (int k=0;k<HD;k++){
            F4U wv; wv.f = gP1ih[k*HD+j];
            #pragma unroll
            for (int b=0;b<NB;b++){
                u64 x2 = pk2(h0s[b][k]);
                ffma2(aLo[b], wv.u.x, x2);
                ffma2(aHi[b], wv.u.y, x2);
            }
        }
        #pragma unroll 4
        for (int k=0;k<HD;k++){
            F4U wv; wv.f = gP1hh[k*HD+j];
            #pragma unroll
            for (int b=0;b<NB;b++){
                u64 x2 = pk2(h1s[b][k]);
                ffma2(aLo[b], wv.u.x, x2);
                ffma2(aHi[b], wv.u.y, x2);
            }
        }
        #pragma unroll
        for (int b=0;b<NB;b++){
            float2 ifg = up2(aLo[b]);
            float2 go  = up2(aHi[b]);
            float ii=sigf(ifg.x), ff=sigf(ifg.y);
            float gg=tanhf(go.x),  oo=sigf(go.y);
            c1[b]=ff*c1[b]+ii*gg;
            hn[b]=oo*tanhf(c1[b]);
        }
        __syncthreads();
        #pragma unroll
        for (int b=0;b<NB;b++){
            h1s[b][j]=hn[b];
            gH1[(size_t)((b0+b)*TL+t)*HD+j]=hn[b];
        }
        if (j<DA && t+1<TL){
            #pragma unroll
            for (int b=0;b<NB;b++) xs[b][j]=a[((b0+b)*TL+t)*DA+j];
        }
        __syncthreads();
    }
}

// ---------- Kalman scan: register-tiled + packed f32x2, warp-sync GJ ----------
#define ST 36   // stride for 32-col tiles (float4-aligned: 144B rows)

__global__ void __launch_bounds__(128) k_kalman(const float* __restrict__ a,
                                                const float* __restrict__ Am,
                                                const float* __restrict__ Cg,
                                                const float* __restrict__ Wlin,
                                                const float* __restrict__ blin,
                                                float* __restrict__ out)
{
    const int tid  = threadIdx.x;
    const int b    = blockIdx.x;
    const int wd   = tid >> 5;
    const int lane = tid & 31;
    const int cgp  = tid & 7;        // col group (4 cols)
    const int rr8  = tid >> 3;       // row pair (0..15)
    const int r0   = rr8*2, r1 = r0+1, c0 = cgp*4;

    __shared__ __align__(16) float Sg [DZ][ST];
    __shared__ __align__(16) float W1 [DZ][ST];
    __shared__ __align__(16) float W2 [DZ][ST];
    __shared__ __align__(16) float An [DZ][ST];
    __shared__ __align__(16) float AnT[DZ][ST];
    __shared__ __align__(16) float Jm [DZ][ST];
    __shared__ __align__(16) float JmT[DZ][ST];
    __shared__ __align__(16) float Cx [DA][ST];
    __shared__ __align__(16) float Mx [DA][ST];
    __shared__ __align__(16) float Kg [DZ][20];
    __shared__ float Sa[DA][18];
    __shared__ __align__(16) float Si[DA][20];
    __shared__ float alw[TL][4];
    __shared__ float wl[3][HD];
    __shared__ float mu[DZ], mu2[DZ], rres[DA], atv[DA];

    // ---- prologue: alphas for all t of this batch element ----
    for (int e = tid; e < 3*HD; e += 128) wl[e>>7][e&127] = Wlin[e];
    __syncthreads();
    {
        const float bl0 = blin[0], bl1 = blin[1], bl2 = blin[2];
        for (int t = wd; t < TL; t += 4){
            const float* h = gH1 + ((size_t)b*TL + t)*HD;
            float s0=0.f, s1=0.f, s2=0.f;
            for (int k = lane; k < HD; k += 32){
                float hv = h[k];
                s0 = fmaf(wl[0][k], hv, s0);
                s1 = fmaf(wl[1][k], hv, s1);
                s2 = fmaf(wl[2][k], hv, s2);
            }
            #pragma unroll
            for (int o = 16; o; o >>= 1){
                s0 += __shfl_down_sync(0xffffffffu, s0, o);
                s1 += __shfl_down_sync(0xffffffffu, s1, o);
                s2 += __shfl_down_sync(0xffffffffu, s2, o);
            }
            if (lane == 0){
                s0 += bl0; s1 += bl1; s2 += bl2;
                float m  = fmaxf(s0, fmaxf(s1, s2));
                float e0 = __expf(s0-m), e1 = __expf(s1-m), e2 = __expf(s2-m);
                float inv = 1.f/(e0+e1+e2);
                alw[t][0]=e0*inv; alw[t][1]=e1*inv; alw[t][2]=e2*inv;
            }
        }
    }
    // ---- init state ----
    for (int e = tid; e < DZ*DZ; e += 128){
        int i = e >> 5, j = e & 31;
        Sg[i][j] = (i==j) ? 1.f : 0.f;
    }
    if (tid < DZ) mu[tid] = 0.f;
    __syncthreads();

    const size_t strC = (size_t)TL*DA*DZ, strA = (size_t)TL*DZ*DZ;

    for (int t = 0; t < TL; t++){
        const int tn = (t+1 < TL) ? (t+1) : (TL-1);
        if (tid < DA) atv[tid] = a[(b*TL+t)*DA + tid];
        const float a0v = alw[t][0],  a1v = alw[t][1],  a2v = alw[t][2];
        const float d0v = alw[tn][0], d1v = alw[tn][1], d2v = alw[tn][2];

        // phase 1: mix Cx (alpha_t), An/AnT (alpha_{t+1})
        for (int e = tid; e < DA*DZ; e += 128){
            int i = e >> 5, j = e & 31;
            const float* p = Cg + ((size_t)t*DA + i)*DZ + j;
            Cx[i][j] = a0v*p[0] + a1v*p[strC] + a2v*p[2*strC];
        }
        for (int e = tid; e < DZ*DZ; e += 128){
            int i = e >> 5, j = e & 31;
            const float* p = Am + ((size_t)tn*DZ + i)*DZ + j;
            float v = d0v*p[0] + d1v*p[strA] + d2v*p[2*strA];
            An[i][j] = v;  AnT[j][i] = v;
        }
        __syncthreads();

        // phase 2: Mx = Cx*Sg (16x32, packed); rres = a - Cx*mu
        {
            int i = tid >> 3;
            u64 lo = 0ull, hi = 0ull;
            #pragma unroll 8
            for (int k = 0; k < DZ; k++){
                ulonglong2 sv = *reinterpret_cast<const ulonglong2*>(&Sg[k][c0]);
                u64 x2 = pk2(Cx[i][k]);
                ffma2(lo, sv.x, x2);
                ffma2(hi, sv.y, x2);
            }
            F4U o; o.u.x = lo; o.u.y = hi;
            *reinterpret_cast<float4*>(&Mx[i][c0]) = o.f;
        }
        if (tid < DA){
            float s = atv[tid];
            #pragma unroll 8
            for (int k = 0; k < DZ; k++) s = fmaf(-Cx[tid][k], mu[k], s);
            rres[tid] = s;
        }
        __syncthreads();

        // phase 3: S = Mx*Cx^T + 0.01 I  (16x16, horizontal dots, scalar)
        {
            int i = tid >> 3, j0 = (tid & 7)*2;
            float s0 = 0.f, s1 = 0.f;
            #pragma unroll
            for (int kq = 0; kq < 8; kq++){
                float4 m  = *reinterpret_cast<const float4*>(&Mx[i][kq*4]);
                float4 ca = *reinterpret_cast<const float4*>(&Cx[j0][kq*4]);
                float4 cb = *reinterpret_cast<const float4*>(&Cx[j0+1][kq*4]);
                s0 = fmaf(m.x,ca.x, fmaf(m.y,ca.y, fmaf(m.z,ca.z, fmaf(m.w,ca.w, s0))));
                s1 = fmaf(m.x,cb.x, fmaf(m.y,cb.y, fmaf(m.z,cb.z, fmaf(m.w,cb.w, s1))));
            }
            Sa[i][j0]   = s0 + ((i==j0)  ? 0.01f : 0.f);
            Sa[i][j0+1] = s1 + ((i==j0+1)? 0.01f : 0.f);
        }
        __syncthreads();

        // phase 4: warp-0 Gauss-Jordan inverse of S -> Si
        if (wd == 0){
            float Sc[DA], Ic[DA];
            int c = lane & 15;
            #pragma unroll
            for (int i = 0; i < DA; i++){ Sc[i] = Sa[i][c]; Ic[i] = (i==c)?1.f:0.f; }
            #pragma unroll
            for (int p = 0; p < DA; p++){
                float piv  = __shfl_sync(0xffffffffu, Sc[p], p);
                float invp = 1.f/((fabsf(piv) > 1e-30f) ? piv : 1e-30f);
                float ps = Sc[p], pi = Ic[p];
                #pragma unroll
                for (int i = 0; i < DA; i++){
                    if (i == p) continue;
                    float f = __shfl_sync(0xffffffffu, Sc[i], p) * invp;
                    Sc[i] = fmaf(-f, ps, Sc[i]);
                    Ic[i] = fmaf(-f, pi, Ic[i]);
                }
            }
            #pragma unroll
            for (int i = 0; i < DA; i++){
                float d = __shfl_sync(0xffffffffu, Sc[i], i);
                Ic[i] /= ((fabsf(d) > 1e-30f) ? d : 1e-30f);
            }
            if (lane < DA){
                #pragma unroll
                for (int i = 0; i < DA; i++) Si[i][lane] = Ic[i];
            }
        }
        __syncthreads();

        // phase 5: Kg = Mx^T * Si  (32x16, packed)
        {
            int z = tid >> 2, dg = (tid & 3)*4;
            u64 lo = 0ull, hi = 0ull;
            #pragma unroll
            for (int k = 0; k < DA; k++){
                ulonglong2 bv = *reinterpret_cast<const ulonglong2*>(&Si[k][dg]);
                u64 x2 = pk2(Mx[k][z]);
                ffma2(lo, bv.x, x2);
                ffma2(hi, bv.y, x2);
            }
            F4U o; o.u.x = lo; o.u.y = hi;
            *reinterpret_cast<float4*>(&Kg[z][dg]) = o.f;
        }
        __syncthreads();

        // phase 6: Jm = I - Kg*Cx (+JmT, packed); mu2 = mu + Kg*rres (OUTPUT)
        {
            F4U iA, iB;
            iA.f = make_float4((r0==c0)?1.f:0.f, (r0==c0+1)?1.f:0.f,
                               (r0==c0+2)?1.f:0.f, (r0==c0+3)?1.f:0.f);
            iB.f = make_float4((r1==c0)?1.f:0.f, (r1==c0+1)?1.f:0.f,
                               (r1==c0+2)?1.f:0.f, (r1==c0+3)?1.f:0.f);
            u64 aLo=iA.u.x, aHi=iA.u.y, bLo=iB.u.x, bHi=iB.u.y;
            #pragma unroll
            for (int d = 0; d < DA; d++){
                ulonglong2 cv = *reinterpret_cast<const ulonglong2*>(&Cx[d][c0]);
                u64 xA = pk2(-Kg[r0][d]), xB = pk2(-Kg[r1][d]);
                ffma2(aLo, cv.x, xA);  ffma2(aHi, cv.y, xA);
                ffma2(bLo, cv.x, xB);  ffma2(bHi, cv.y, xB);
            }
            F4U oA, oB; oA.u.x=aLo; oA.u.y=aHi; oB.u.x=bLo; oB.u.y=bHi;
            *reinterpret_cast<float4*>(&Jm[r0][c0]) = oA.f;
            *reinterpret_cast<float4*>(&Jm[r1][c0]) = oB.f;
            JmT[c0  ][r0]=oA.f.x; JmT[c0+1][r0]=oA.f.y; JmT[c0+2][r0]=oA.f.z; JmT[c0+3][r0]=oA.f.w;
            JmT[c0  ][r1]=oB.f.x; JmT[c0+1][r1]=oB.f.y; JmT[c0+2][r1]=oB.f.z; JmT[c0+3][r1]=oB.f.w;
        }
        if (tid < DZ){
            float s = mu[tid];
            #pragma unroll
            for (int d = 0; d < DA; d++) s = fmaf(Kg[tid][d], rres[d], s);
            s = clamp4(s);
            mu2[tid] = s;
            out[((size_t)b*TL + t)*DZ + tid] = s;
        }
        __syncthreads();

        // phase 7: W1 = Jm*Sg (packed)
        {
            u64 aLo=0ull, aHi=0ull, bLo=0ull, bHi=0ull;
            #pragma unroll 8
            for (int k = 0; k < DZ; k++){
                ulonglong2 sv = *reinterpret_cast<const ulonglong2*>(&Sg[k][c0]);
                u64 xA = pk2(Jm[r0][k]), xB = pk2(Jm[r1][k]);
                ffma2(aLo, sv.x, xA);  ffma2(aHi, sv.y, xA);
                ffma2(bLo, sv.x, xB);  ffma2(bHi, sv.y, xB);
            }
            F4U oA, oB; oA.u.x=aLo; oA.u.y=aHi; oB.u.x=bLo; oB.u.y=bHi;
            *reinterpret_cast<float4*>(&W1[r0][c0]) = oA.f;
            *reinterpret_cast<float4*>(&W1[r1][c0]) = oB.f;
        }
        __syncthreads();

        // phase 8: W2 = W1*Jm^T + 0.01*Kg*Kg^T   (Joseph form; main loop packed)
        {
            u64 aLo=0ull, aHi=0ull, bLo=0ull, bHi=0ull;
            #pragma unroll 8
            for (int k = 0; k < DZ; k++){
                ulonglong2 jv = *reinterpret_cast<const ulonglong2*>(&JmT[k][c0]);
                u64 xA = pk2(W1[r0][k]), xB = pk2(W1[r1][k]);
                ffma2(aLo, jv.x, xA);  ffma2(aHi, jv.y, xA);
                ffma2(bLo, jv.x, xB);  ffma2(bHi, jv.y, xB);
            }
            float4 qA = make_float4(0,0,0,0), qB = make_float4(0,0,0,0);
            #pragma unroll
            for (int dq = 0; dq < 4; dq++){
                float4 ka = *reinterpret_cast<const float4*>(&Kg[r0][dq*4]);
                float4 kb = *reinterpret_cast<const float4*>(&Kg[r1][dq*4]);
                float4 kc0 = *reinterpret_cast<const float4*>(&Kg[c0  ][dq*4]);
                float4 kc1 = *reinterpret_cast<const float4*>(&Kg[c0+1][dq*4]);
                float4 kc2 = *reinterpret_cast<const float4*>(&Kg[c0+2][dq*4]);
                float4 kc3 = *reinterpret_cast<const float4*>(&Kg[c0+3][dq*4]);
                qA.x = fmaf(ka.x,kc0.x,fmaf(ka.y,kc0.y,fmaf(ka.z,kc0.z,fmaf(ka.w,kc0.w,qA.x))));
                qA.y = fmaf(ka.x,kc1.x,fmaf(ka.y,kc1.y,fmaf(ka.z,kc1.z,fmaf(ka.w,kc1.w,qA.y))));
                qA.z = fmaf(ka.x,kc2.x,fmaf(ka.y,kc2.y,fmaf(ka.z,kc2.z,fmaf(ka.w,kc2.w,qA.z))));
                qA.w = fmaf(ka.x,kc3.x,fmaf(ka.y,kc3.y,fmaf(ka.z,kc3.z,fmaf(ka.w,kc3.w,qA.w))));
                qB.x = fmaf(kb.x,kc0.x,fmaf(kb.y,kc0.y,fmaf(kb.z,kc0.z,fmaf(kb.w,kc0.w,qB.x))));
                qB.y = fmaf(kb.x,kc1.x,fmaf(kb.y,kc1.y,fmaf(kb.z,kc1.z,fmaf(kb.w,kc1.w,qB.y))));
                qB.z = fmaf(kb.x,kc2.x,fmaf(kb.y,kc2.y,fmaf(kb.z,kc2.z,fmaf(kb.w,kc2.w,qB.z))));
                qB.w = fmaf(kb.x,kc3.x,fmaf(kb.y,kc3.y,fmaf(kb.z,kc3.z,fmaf(kb.w,kc3.w,qB.w))));
            }
            F4U oA, oB; oA.u.x=aLo; oA.u.y=aHi; oB.u.x=bLo; oB.u.y=bHi;
            oA.f.x += 0.01f*qA.x; oA.f.y += 0.01f*qA.y; oA.f.z += 0.01f*qA.z; oA.f.w += 0.01f*qA.w;
            oB.f.x += 0.01f*qB.x; oB.f.y += 0.01f*qB.y; oB.f.z += 0.01f*qB.z; oB.f.w += 0.01f*qB.w;
            *reinterpret_cast<float4*>(&W2[r0][c0]) = oA.f;
            *reinterpret_cast<float4*>(&W2[r1][c0]) = oB.f;
        }
        __syncthreads();

        // phase 9: W1 = sym(W2)  (Sigma_post)
        {
            #pragma unroll
            for (int q = 0; q < 4; q++){
                W1[r0][c0+q] = 0.5f*(W2[r0][c0+q] + W2[c0+q][r0]);
                W1[r1][c0+q] = 0.5f*(W2[r1][c0+q] + W2[c0+q][r1]);
            }
        }
        __syncthreads();

        // phase 10: W2 = An * Sigma_post (packed)
        {
            u64 aLo=0ull, aHi=0ull, bLo=0ull, bHi=0ull;
            #pragma unroll 8
            for (int k = 0; k < DZ; k++){
                ulonglong2 wv = *reinterpret_cast<const ulonglong2*>(&W1[k][c0]);
                u64 xA = pk2(An[r0][k]), xB = pk2(An[r1][k]);
                ffma2(aLo, wv.x, xA);  ffma2(aHi, wv.y, xA);
                ffma2(bLo, wv.x, xB);  ffma2(bHi, wv.y, xB);
            }
            F4U oA, oB; oA.u.x=aLo; oA.u.y=aHi; oB.u.x=bLo; oB.u.y=bHi;
            *reinterpret_cast<float4*>(&W2[r0][c0]) = oA.f;
            *reinterpret_cast<float4*>(&W2[r1][c0]) = oB.f;
        }
        __syncthreads();

        // phase 11: Sg = W2*An^T + 0.01 I (packed); mu' = An*mu2
        {
            F4U iA, iB;
            iA.f = make_float4((r0==c0)?0.01f:0.f, (r0==c0+1)?0.01f:0.f,
                               (r0==c0+2)?0.01f:0.f, (r0==c0+3)?0.01f:0.f);
            iB.f = make_float4((r1==c0)?0.01f:0.f, (r1==c0+1)?0.01f:0.f,
                               (r1==c0+2)?0.01f:0.f, (r1==c0+3)?0.01f:0.f);
            u64 aLo=iA.u.x, aHi=iA.u.y, bLo=iB.u.x, bHi=iB.u.y;
            #pragma unroll 8
            for (int k = 0; k < DZ; k++){
                ulonglong2 av = *reinterpret_cast<const ulonglong2*>(&AnT[k][c0]);
                u64 xA = pk2(W2[r0][k]), xB = pk2(W2[r1][k]);
                ffma2(aLo, av.x, xA);  ffma2(aHi, av.y, xA);
                ffma2(bLo, av.x, xB);  ffma2(bHi, av.y, xB);
            }
            F4U oA, oB; oA.u.x=aLo; oA.u.y=aHi; oB.u.x=bLo; oB.u.y=bHi;
            oA.f.x=clamp4(oA.f.x); oA.f.y=clamp4(oA.f.y); oA.f.z=clamp4(oA.f.z); oA.f.w=clamp4(oA.f.w);
            oB.f.x=clamp4(oB.f.x); oB.f.y=clamp4(oB.f.y); oB.f.z=clamp4(oB.f.z); oB.f.w=clamp4(oB.f.w);
            *reinterpret_cast<float4*>(&Sg[r0][c0]) = oA.f;
            *reinterpret_cast<float4*>(&Sg[r1][c0]) = oB.f;
        }
        if (tid < DZ){
            float s = 0.f;
            #pragma unroll 8
            for (int k = 0; k < DZ; k++) s = fmaf(An[tid][k], mu2[k], s);
            mu[tid] = clamp4(s);
        }
        __syncthreads();
    }
}

extern "C" void kernel_launch(void* const* d_in, const int* in_sizes, int n_in,
                              void* d_out, int out_size)
{
    // dict order: a, A, C, a0, Wih0, Whh0, bih0, bhh0, Wih1, Whh1, bih1, bhh1, Wlin, blin
    static const int sig_dict[14] = {1048576,393216,196608,16,8192,65536,512,512,65536,65536,512,512,384,3};
    static const int sig_ascii[14] = {393216,196608,65536,65536,8192,65536,384,1048576,16,512,512,512,512,3};
    static const int map_dict[14]  = {0,1,2,3,4,5,6,7,8,9,10,11,12,13};
    static const int map_ascii[14] = {7,0,1,8,4,2,11,9,5,3,12,10,6,13};

    const int* map = map_dict;
    if (n_in >= 14){
        bool d=true, s=true;
        for (int i=0;i<14;i++){
            if (in_sizes[i]!=sig_dict[i])  d=false;
            if (in_sizes[i]!=sig_ascii[i]) s=false;
        }
        if (!d && s) map = map_ascii;
    }

    const float* a    = (const float*)d_in[map[0]];
    const float* A    = (const float*)d_in[map[1]];
    const float* C    = (const float*)d_in[map[2]];
    const float* a0   = (const float*)d_in[map[3]];
    const float* Wih0 = (const float*)d_in[map[4]];
    const float* Whh0 = (const float*)d_in[map[5]];
    const float* bih0 = (const float*)d_in[map[6]];
    const float* bhh0 = (const float*)d_in[map[7]];
    const float* Wih1 = (const float*)d_in[map[8]];
    const float* Whh1 = (const float*)d_in[map[9]];
    const float* bih1 = (const float*)d_in[map[10]];
    const float* bhh1 = (const float*)d_in[map[11]];
    const float* Wlin = (const float*)d_in[map[12]];
    const float* blin = (const float*)d_in[map[13]];

    k_prep  <<<64, 256>>>(Wih0,Whh0,Wih1,Whh1,bih0,bhh0,bih1,bhh1);
    k_lstm  <<<BS/NB, HD>>>(a, a0);
    k_kalman<<<BS, 128>>>(a, A, C, Wlin, blin, (float*)d_out);
}